// round 1
// baseline (speedup 1.0000x reference)
#include <cuda_runtime.h>
#include <math.h>

// Problem constants
#define BATCH 4
#define SEQ   2048
#define DIM   1024
#define MROWS (BATCH*SEQ)   // 8192

// SGEMM tiling
#define BM 128
#define BN 128
#define BK 8
#define TM 8
#define TN 8
// 256 threads per block, each computes an 8x8 microtile.

// Scratch (static device allocations are allowed; runtime alloc is not)
__device__ float g_Q[BATCH*SEQ*DIM];
__device__ float g_K[BATCH*SEQ*DIM];
__device__ float g_V[BATCH*SEQ*DIM];
__device__ float g_P[(size_t)BATCH*SEQ*SEQ];
__device__ float g_O[BATCH*SEQ*DIM];

// ---------------------------------------------------------------------------
// NT SGEMM: C[m,n] = sum_k A[m,k] * B[n,k]  (+ optional bias[n])
// A: [M,K] row-major, B: [N,K] row-major, C: [M,N] row-major.
// M,N multiples of 128; K multiple of 8.
// ---------------------------------------------------------------------------
__global__ void __launch_bounds__(256)
k_gemm_nt(const float* __restrict__ A, const float* __restrict__ B,
          float* __restrict__ C, int M, int N, int K,
          const float* __restrict__ bias)
{
    __shared__ float As[BK][BM];
    __shared__ float Bs[BK][BN];

    const int tid = threadIdx.x;
    const int tx = tid & 15;        // 0..15 (n dir)
    const int ty = tid >> 4;        // 0..15 (m dir)
    const int m0 = blockIdx.y * BM;
    const int n0 = blockIdx.x * BN;

    const int lrow = tid >> 1;      // 0..127
    const int lcol = (tid & 1) * 4; // 0 or 4

    const float* Ag = A + (size_t)(m0 + lrow) * K + lcol;
    const float* Bg = B + (size_t)(n0 + lrow) * K + lcol;

    float acc[TM][TN] = {};

    for (int k0 = 0; k0 < K; k0 += BK) {
        float4 av = *(const float4*)(Ag + k0);
        float4 bv = *(const float4*)(Bg + k0);
        As[lcol+0][lrow] = av.x; As[lcol+1][lrow] = av.y;
        As[lcol+2][lrow] = av.z; As[lcol+3][lrow] = av.w;
        Bs[lcol+0][lrow] = bv.x; Bs[lcol+1][lrow] = bv.y;
        Bs[lcol+2][lrow] = bv.z; Bs[lcol+3][lrow] = bv.w;
        __syncthreads();
        #pragma unroll
        for (int k = 0; k < BK; ++k) {
            float a[TM], b[TN];
            #pragma unroll
            for (int i = 0; i < TM; ++i) a[i] = As[k][ty*TM + i];
            #pragma unroll
            for (int j = 0; j < TN; ++j) b[j] = Bs[k][tx*TN + j];
            #pragma unroll
            for (int i = 0; i < TM; ++i)
                #pragma unroll
                for (int j = 0; j < TN; ++j)
                    acc[i][j] = fmaf(a[i], b[j], acc[i][j]);
        }
        __syncthreads();
    }

    #pragma unroll
    for (int i = 0; i < TM; ++i) {
        const int m = m0 + ty*TM + i;
        float* Cr = C + (size_t)m * N + n0 + tx*TN;
        #pragma unroll
        for (int j = 0; j < TN; ++j) {
            float v = acc[i][j];
            if (bias) v += bias[n0 + tx*TN + j];
            Cr[j] = v;
        }
    }
}

// ---------------------------------------------------------------------------
// Causal scores: P[b,q,k] = sum_d Q[b,q,d]*K[b,k,d], only for block tiles
// touching the lower triangle. Fully-masked tiles are skipped entirely
// (softmax never reads k > q, so in-tile masked entries may hold garbage).
// ---------------------------------------------------------------------------
__global__ void __launch_bounds__(256)
k_scores_causal(const float* __restrict__ Qg, const float* __restrict__ Kg,
                float* __restrict__ Pg, int S, int D)
{
    const int m0 = blockIdx.y * BM;   // q tile
    const int n0 = blockIdx.x * BN;   // k tile
    if (n0 > m0 + BM - 1) return;     // tile fully above diagonal

    const int b = blockIdx.z;
    const float* A = Qg + (size_t)b * S * D;
    const float* B = Kg + (size_t)b * S * D;
    float* C = Pg + (size_t)b * S * S;

    __shared__ float As[BK][BM];
    __shared__ float Bs[BK][BN];

    const int tid = threadIdx.x;
    const int tx = tid & 15;
    const int ty = tid >> 4;
    const int lrow = tid >> 1;
    const int lcol = (tid & 1) * 4;

    const float* Ag = A + (size_t)(m0 + lrow) * D + lcol;
    const float* Bg = B + (size_t)(n0 + lrow) * D + lcol;

    float acc[TM][TN] = {};

    for (int k0 = 0; k0 < D; k0 += BK) {
        float4 av = *(const float4*)(Ag + k0);
        float4 bv = *(const float4*)(Bg + k0);
        As[lcol+0][lrow] = av.x; As[lcol+1][lrow] = av.y;
        As[lcol+2][lrow] = av.z; As[lcol+3][lrow] = av.w;
        Bs[lcol+0][lrow] = bv.x; Bs[lcol+1][lrow] = bv.y;
        Bs[lcol+2][lrow] = bv.z; Bs[lcol+3][lrow] = bv.w;
        __syncthreads();
        #pragma unroll
        for (int k = 0; k < BK; ++k) {
            float a[TM], bb[TN];
            #pragma unroll
            for (int i = 0; i < TM; ++i) a[i] = As[k][ty*TM + i];
            #pragma unroll
            for (int j = 0; j < TN; ++j) bb[j] = Bs[k][tx*TN + j];
            #pragma unroll
            for (int i = 0; i < TM; ++i)
                #pragma unroll
                for (int j = 0; j < TN; ++j)
                    acc[i][j] = fmaf(a[i], bb[j], acc[i][j]);
        }
        __syncthreads();
    }

    #pragma unroll
    for (int i = 0; i < TM; ++i) {
        const int m = m0 + ty*TM + i;
        float* Cr = C + (size_t)m * S + n0 + tx*TN;
        #pragma unroll
        for (int j = 0; j < TN; ++j) Cr[j] = acc[i][j];
    }
}

// ---------------------------------------------------------------------------
// Row softmax over the causal-valid prefix [0, row]. Zeros [row+1, next 128
// boundary) so the PV GEMM can run its K loop to the tile boundary.
// ---------------------------------------------------------------------------
__global__ void __launch_bounds__(256)
k_softmax(float* __restrict__ Pg, int S)
{
    const int b = blockIdx.z;
    const int row = blockIdx.x;
    float* r = Pg + ((size_t)b * S + row) * S;
    const int len = row + 1;
    const int tid = threadIdx.x;

    __shared__ float red[8];

    float m = -INFINITY;
    for (int i = tid; i < len; i += 256) m = fmaxf(m, r[i]);
    #pragma unroll
    for (int o = 16; o; o >>= 1) m = fmaxf(m, __shfl_xor_sync(0xffffffffu, m, o));
    if ((tid & 31) == 0) red[tid >> 5] = m;
    __syncthreads();
    float mm = -INFINITY;
    #pragma unroll
    for (int i = 0; i < 8; ++i) mm = fmaxf(mm, red[i]);
    __syncthreads();

    float s = 0.f;
    for (int i = tid; i < len; i += 256) {
        float e = __expf(r[i] - mm);
        r[i] = e;
        s += e;
    }
    #pragma unroll
    for (int o = 16; o; o >>= 1) s += __shfl_xor_sync(0xffffffffu, s, o);
    if ((tid & 31) == 0) red[tid >> 5] = s;
    __syncthreads();
    float ss = 0.f;
    #pragma unroll
    for (int i = 0; i < 8; ++i) ss += red[i];
    const float inv = 1.f / ss;

    for (int i = tid; i < len; i += 256) r[i] *= inv;
    const int zend = ((row >> 7) + 1) << 7;   // next 128 boundary
    for (int i = len + tid; i < zend; i += 256) r[i] = 0.f;
}

// ---------------------------------------------------------------------------
// NN SGEMM for O = P @ V with K-loop bounded at the causal tile boundary.
// P: [S,S] row-major, V: [S,D] row-major, O: [S,D] row-major (per batch).
// ---------------------------------------------------------------------------
__global__ void __launch_bounds__(256)
k_pv(const float* __restrict__ Pg, const float* __restrict__ Vg,
     float* __restrict__ Og, int S, int D)
{
    const int b = blockIdx.z;
    const float* A = Pg + (size_t)b * S * S;
    const float* B = Vg + (size_t)b * S * D;
    float* C = Og + (size_t)b * S * D;

    __shared__ float As[BK][BM];
    __shared__ float Bs[BK][BN];

    const int tid = threadIdx.x;
    const int tx = tid & 15;
    const int ty = tid >> 4;
    const int m0 = blockIdx.y * BM;   // q tile
    const int n0 = blockIdx.x * BN;   // d tile

    // A tile load (transpose into smem)
    const int lrow = tid >> 1;
    const int lcol = (tid & 1) * 4;
    const float* Ag = A + (size_t)(m0 + lrow) * S + lcol;

    // B tile load (direct, NN)
    const int krow = tid >> 5;        // 0..7
    const int ncol = (tid & 31) * 4;  // 0..124
    const float* Bg = B + (size_t)krow * D + n0 + ncol;

    const int kmax = m0 + BM;         // P[q,k]==0 for k >= this per tile row

    float acc[TM][TN] = {};

    for (int k0 = 0; k0 < kmax; k0 += BK) {
        float4 av = *(const float4*)(Ag + k0);
        float4 bv = *(const float4*)(Bg + (size_t)k0 * D);
        As[lcol+0][lrow] = av.x; As[lcol+1][lrow] = av.y;
        As[lcol+2][lrow] = av.z; As[lcol+3][lrow] = av.w;
        *(float4*)&Bs[krow][ncol] = bv;
        __syncthreads();
        #pragma unroll
        for (int k = 0; k < BK; ++k) {
            float a[TM], bb[TN];
            #pragma unroll
            for (int i = 0; i < TM; ++i) a[i] = As[k][ty*TM + i];
            #pragma unroll
            for (int j = 0; j < TN; ++j) bb[j] = Bs[k][tx*TN + j];
            #pragma unroll
            for (int i = 0; i < TM; ++i)
                #pragma unroll
                for (int j = 0; j < TN; ++j)
                    acc[i][j] = fmaf(a[i], bb[j], acc[i][j]);
        }
        __syncthreads();
    }

    #pragma unroll
    for (int i = 0; i < TM; ++i) {
        const int m = m0 + ty*TM + i;
        float* Cr = C + (size_t)m * D + n0 + tx*TN;
        #pragma unroll
        for (int j = 0; j < TN; ++j) Cr[j] = acc[i][j];
    }
}

// ---------------------------------------------------------------------------
extern "C" void kernel_launch(void* const* d_in, const int* in_sizes, int n_in,
                              void* d_out, int out_size)
{
    const float* x  = (const float*)d_in[0];
    const float* WQ = (const float*)d_in[1];
    const float* WK = (const float*)d_in[2];
    const float* WV = (const float*)d_in[3];
    const float* WO = (const float*)d_in[4];
    const float* bO = (const float*)d_in[5];
    float* out = (float*)d_out;

    float *Q, *K, *V, *P, *O;
    cudaGetSymbolAddress((void**)&Q, g_Q);
    cudaGetSymbolAddress((void**)&K, g_K);
    cudaGetSymbolAddress((void**)&V, g_V);
    cudaGetSymbolAddress((void**)&P, g_P);
    cudaGetSymbolAddress((void**)&O, g_O);

    dim3 blk(256);

    // QKV projections: [8192,1024] x [1024,1024]^T
    dim3 gproj(DIM / BN, MROWS / BM);
    k_gemm_nt<<<gproj, blk>>>(x, WQ, Q, MROWS, DIM, DIM, nullptr);
    k_gemm_nt<<<gproj, blk>>>(x, WK, K, MROWS, DIM, DIM, nullptr);
    k_gemm_nt<<<gproj, blk>>>(x, WV, V, MROWS, DIM, DIM, nullptr);

    // Causal scores per batch (above-diagonal tiles skipped inside kernel)
    k_scores_causal<<<dim3(SEQ / BN, SEQ / BM, BATCH), blk>>>(Q, K, P, SEQ, DIM);

    // Row softmax over valid prefix
    k_softmax<<<dim3(SEQ, 1, BATCH), blk>>>(P, SEQ);

    // O = P @ V, K-loop bounded by causal tile boundary
    k_pv<<<dim3(DIM / BN, SEQ / BM, BATCH), blk>>>(P, V, O, SEQ, DIM);

    // Output projection + bias
    k_gemm_nt<<<gproj, blk>>>(O, WO, out, MROWS, DIM, DIM, bO);
}

// round 3
// speedup vs baseline: 2.7189x; 2.7189x over previous
#include <cuda_runtime.h>
#include <cuda_bf16.h>
#include <math.h>
#include <stdint.h>

#define BATCH 4
#define SEQ   2048
#define DIM   1024
#define MROWS (BATCH*SEQ)   // 8192

// ---------------------------------------------------------------------------
// Scratch (__device__ globals; runtime allocation is forbidden)
// ---------------------------------------------------------------------------
__device__ __nv_bfloat16 g_xhi[MROWS*DIM],  g_xlo[MROWS*DIM];
__device__ __nv_bfloat16 g_Wqhi[DIM*DIM],   g_Wqlo[DIM*DIM];
__device__ __nv_bfloat16 g_Wkhi[DIM*DIM],   g_Wklo[DIM*DIM];
__device__ __nv_bfloat16 g_Wvhi[DIM*DIM],   g_Wvlo[DIM*DIM];
__device__ __nv_bfloat16 g_Wohi[DIM*DIM],   g_Wolo[DIM*DIM];
__device__ __nv_bfloat16 g_Qhi[MROWS*DIM],  g_Qlo[MROWS*DIM];
__device__ __nv_bfloat16 g_Khi[MROWS*DIM],  g_Klo[MROWS*DIM];
__device__ __nv_bfloat16 g_Vthi[MROWS*DIM], g_Vtlo[MROWS*DIM];   // [B, D, S]
__device__ float         g_Pf[(size_t)BATCH*SEQ*SEQ];
__device__ __nv_bfloat16 g_Phi[(size_t)BATCH*SEQ*SEQ], g_Plo[(size_t)BATCH*SEQ*SEQ];
__device__ __nv_bfloat16 g_Ohi[MROWS*DIM],  g_Olo[MROWS*DIM];

// ---------------------------------------------------------------------------
// Helpers
// ---------------------------------------------------------------------------
__device__ __forceinline__ uint32_t smem_u32(const void* p) {
    uint32_t a;
    asm("{ .reg .u64 t; cvta.to.shared.u64 t, %1; cvt.u32.u64 %0, t; }" : "=r"(a) : "l"(p));
    return a;
}

// XOR swizzle for 64B-row tiles (8 rows x 64B atom): conflict-free ldmatrix
#define SWZ64(off) ((uint32_t)(off) ^ (((uint32_t)(off) >> 3) & 0x30))

#define CP16(dst, src) \
    asm volatile("cp.async.cg.shared.global [%0], [%1], 16;" :: "r"(dst), "l"(src))
#define CPCOMMIT() asm volatile("cp.async.commit_group;" ::: "memory")
#define CPWAIT(n)  asm volatile("cp.async.wait_group %0;" :: "n"(n) : "memory")

__device__ __forceinline__ void ldm4(uint32_t* r, uint32_t addr) {
    asm volatile("ldmatrix.sync.aligned.m8n8.x4.shared.b16 {%0,%1,%2,%3}, [%4];"
        : "=r"(r[0]), "=r"(r[1]), "=r"(r[2]), "=r"(r[3]) : "r"(addr));
}

__device__ __forceinline__ void mma16816(float* c, const uint32_t* a, const uint32_t* b) {
    asm volatile("mma.sync.aligned.m16n8k16.row.col.f32.bf16.bf16.f32 "
        "{%0,%1,%2,%3}, {%4,%5,%6,%7}, {%8,%9}, {%0,%1,%2,%3};"
        : "+f"(c[0]), "+f"(c[1]), "+f"(c[2]), "+f"(c[3])
        : "r"(a[0]), "r"(a[1]), "r"(a[2]), "r"(a[3]), "r"(b[0]), "r"(b[1]));
}

// ---------------------------------------------------------------------------
// Tensor-core GEMM: C(128x128) = A * B^T, 3-MMA bf16 split precision.
// A: [rows, Kdim] hi/lo bf16 K-major; B: [rows, Kdim] hi/lo bf16 K-major.
// EPI: 0 = fp32 out (+bias), 1 = bf16 hi/lo out, 2 = bf16 hi/lo transposed (V)
// ---------------------------------------------------------------------------
#define STAGE_BYTES 32768
#define OFF_AHI 0
#define OFF_ALO 8192
#define OFF_BHI 16384
#define OFF_BLO 24576
#define SMEM_BYTES 65536

template<int EPI, bool CAUSAL, bool KBOUND, bool HASBIAS>
__global__ void __launch_bounds__(256)
k_tc(const __nv_bfloat16* __restrict__ Ahi, const __nv_bfloat16* __restrict__ Alo,
     const __nv_bfloat16* __restrict__ Bhi, const __nv_bfloat16* __restrict__ Blo,
     float* __restrict__ Cf, __nv_bfloat16* __restrict__ Chi, __nv_bfloat16* __restrict__ Clo,
     const float* __restrict__ bias,
     int N, int Kdim, long long sA, long long sB, long long sC)
{
    const int m0 = blockIdx.y * 128;
    const int n0 = blockIdx.x * 128;
    if (CAUSAL && n0 > m0) return;
    const long long b = blockIdx.z;
    Ahi += b * sA; Alo += b * sA;
    Bhi += b * sB; Blo += b * sB;

    extern __shared__ char smem[];
    const uint32_t sb = smem_u32(smem);
    const int tid = threadIdx.x, lane = tid & 31, wid = tid >> 5;
    const int wm = wid & 1, wn = wid >> 1;     // warp tile 64(m) x 32(n)

    const int kend = KBOUND ? (m0 + 128) : Kdim;
    const int nchunk = kend >> 5;              // BK = 32

    float acc[4][4][4];
    #pragma unroll
    for (int i = 0; i < 4; ++i)
        #pragma unroll
        for (int j = 0; j < 4; ++j)
            #pragma unroll
            for (int r = 0; r < 4; ++r) acc[i][j][r] = 0.f;

    // stage loader: 4 tiles of 128 rows x 64B, SWZ64 layout, cp.async 16B
    auto load_stage = [&](int c, int s) {
        const int k0 = c << 5;
        const uint32_t sbase = sb + s * STAGE_BYTES;
        #pragma unroll
        for (int h = 0; h < 2; ++h) {
            const int idx = tid + h * 256;     // 0..511
            const int row = idx >> 2, ch = idx & 3;
            const uint32_t so = SWZ64(row * 64 + ch * 16);
            const size_t gA = (size_t)(m0 + row) * Kdim + k0 + ch * 8;
            const size_t gB = (size_t)(n0 + row) * Kdim + k0 + ch * 8;
            CP16(sbase + OFF_AHI + so, Ahi + gA);
            CP16(sbase + OFF_ALO + so, Alo + gA);
            CP16(sbase + OFF_BHI + so, Bhi + gB);
            CP16(sbase + OFF_BLO + so, Blo + gB);
        }
    };

    load_stage(0, 0); CPCOMMIT();

    for (int c = 0; c < nchunk; ++c) {
        const int s = c & 1;
        if (c + 1 < nchunk) { load_stage(c + 1, s ^ 1); CPCOMMIT(); CPWAIT(1); }
        else CPWAIT(0);
        __syncthreads();

        const uint32_t sA = sb + s * STAGE_BYTES;
        #pragma unroll
        for (int kk = 0; kk < 32; kk += 16) {
            uint32_t ahi[4][4], alo[4][4], bhi[4][2], blo[4][2];
            const int arow  = lane & 15;
            const int akoff = (lane >> 4) << 3;
            #pragma unroll
            for (int mt = 0; mt < 4; ++mt) {
                const uint32_t off = SWZ64((wm*64 + mt*16 + arow) * 64 + (kk + akoff) * 2);
                ldm4(ahi[mt], sA + OFF_AHI + off);
                ldm4(alo[mt], sA + OFF_ALO + off);
            }
            const int brow  = (lane & 7) + ((lane & 16) ? 8 : 0);
            const int bkoff = (lane & 8) ? 8 : 0;
            #pragma unroll
            for (int np = 0; np < 2; ++np) {
                const uint32_t off = SWZ64((wn*32 + np*16 + brow) * 64 + (kk + bkoff) * 2);
                uint32_t t4[4];
                ldm4(t4, sA + OFF_BHI + off);
                bhi[np*2][0] = t4[0]; bhi[np*2][1] = t4[1];
                bhi[np*2+1][0] = t4[2]; bhi[np*2+1][1] = t4[3];
                ldm4(t4, sA + OFF_BLO + off);
                blo[np*2][0] = t4[0]; blo[np*2][1] = t4[1];
                blo[np*2+1][0] = t4[2]; blo[np*2+1][1] = t4[3];
            }
            #pragma unroll
            for (int mt = 0; mt < 4; ++mt)
                #pragma unroll
                for (int nt = 0; nt < 4; ++nt) {
                    mma16816(acc[mt][nt], ahi[mt], bhi[nt]);
                    mma16816(acc[mt][nt], ahi[mt], blo[nt]);
                    mma16816(acc[mt][nt], alo[mt], bhi[nt]);
                }
        }
        __syncthreads();
    }

    // Epilogue. C frag: (c0,c1) row g cols t*2,t*2+1; (c2,c3) row g+8.
    const int g = lane >> 2, t = lane & 3;
    #pragma unroll
    for (int mt = 0; mt < 4; ++mt)
        #pragma unroll
        for (int nt = 0; nt < 4; ++nt)
            #pragma unroll
            for (int h = 0; h < 2; ++h) {
                const int m  = m0 + wm*64 + mt*16 + g + h*8;
                const int nb = n0 + wn*32 + nt*8 + t*2;
                float v0 = acc[mt][nt][h*2], v1 = acc[mt][nt][h*2+1];
                if (EPI == 0) {
                    if (HASBIAS) { v0 += bias[nb]; v1 += bias[nb+1]; }
                    float* o = Cf + b*sC + (size_t)m*N + nb;
                    o[0] = v0; o[1] = v1;
                } else if (EPI == 1) {
                    const size_t base = (size_t)(b*sC) + (size_t)m*N + nb;
                    __nv_bfloat16 h0 = __float2bfloat16(v0), h1 = __float2bfloat16(v1);
                    Chi[base]   = h0; Chi[base+1] = h1;
                    Clo[base]   = __float2bfloat16(v0 - __bfloat162float(h0));
                    Clo[base+1] = __float2bfloat16(v1 - __bfloat162float(h1));
                } else {
                    const int bb = m >> 11, sidx = m & 2047;
                    __nv_bfloat16 h0 = __float2bfloat16(v0), h1 = __float2bfloat16(v1);
                    const size_t o0 = ((size_t)bb*DIM + nb)   * SEQ + sidx;
                    const size_t o1 = ((size_t)bb*DIM + nb+1) * SEQ + sidx;
                    Chi[o0] = h0; Clo[o0] = __float2bfloat16(v0 - __bfloat162float(h0));
                    Chi[o1] = h1; Clo[o1] = __float2bfloat16(v1 - __bfloat162float(h1));
                }
            }
}

// ---------------------------------------------------------------------------
// fp32 -> (bf16 hi, bf16 lo) split
// ---------------------------------------------------------------------------
__global__ void __launch_bounds__(256)
k_split(const float* __restrict__ src, __nv_bfloat16* __restrict__ hi,
        __nv_bfloat16* __restrict__ lo, int n)
{
    int i = blockIdx.x * 256 + threadIdx.x;
    if (i < n) {
        float v = src[i];
        __nv_bfloat16 h = __float2bfloat16(v);
        hi[i] = h;
        lo[i] = __float2bfloat16(v - __bfloat162float(h));
    }
}

// ---------------------------------------------------------------------------
// Causal row softmax: fp32 scores -> bf16 hi/lo weights, zero-padded to the
// next 128 boundary (so PV can bound its K loop at the tile edge).
// ---------------------------------------------------------------------------
__global__ void __launch_bounds__(256)
k_softmax(const float* __restrict__ Pf, __nv_bfloat16* __restrict__ Phi,
          __nv_bfloat16* __restrict__ Plo, int S)
{
    const int b = blockIdx.z;
    const int row = blockIdx.x;
    const float* r = Pf + ((size_t)b * S + row) * S;
    __nv_bfloat16* oh = Phi + ((size_t)b * S + row) * S;
    __nv_bfloat16* ol = Plo + ((size_t)b * S + row) * S;
    const int len = row + 1;
    const int tid = threadIdx.x;

    __shared__ float red[8];

    float m = -INFINITY;
    for (int i = tid; i < len; i += 256) m = fmaxf(m, r[i]);
    #pragma unroll
    for (int o = 16; o; o >>= 1) m = fmaxf(m, __shfl_xor_sync(0xffffffffu, m, o));
    if ((tid & 31) == 0) red[tid >> 5] = m;
    __syncthreads();
    float mm = -INFINITY;
    #pragma unroll
    for (int i = 0; i < 8; ++i) mm = fmaxf(mm, red[i]);
    __syncthreads();

    float s = 0.f;
    for (int i = tid; i < len; i += 256) s += __expf(r[i] - mm);
    #pragma unroll
    for (int o = 16; o; o >>= 1) s += __shfl_xor_sync(0xffffffffu, s, o);
    if ((tid & 31) == 0) red[tid >> 5] = s;
    __syncthreads();
    float ss = 0.f;
    #pragma unroll
    for (int i = 0; i < 8; ++i) ss += red[i];
    const float inv = 1.f / ss;

    for (int i = tid; i < len; i += 256) {
        float p = __expf(r[i] - mm) * inv;
        __nv_bfloat16 h = __float2bfloat16(p);
        oh[i] = h;
        ol[i] = __float2bfloat16(p - __bfloat162float(h));
    }
    const int zend = ((row >> 7) + 1) << 7;
    for (int i = len + tid; i < zend; i += 256) {
        oh[i] = __float2bfloat16(0.f);
        ol[i] = __float2bfloat16(0.f);
    }
}

// ---------------------------------------------------------------------------
extern "C" void kernel_launch(void* const* d_in, const int* in_sizes, int n_in,
                              void* d_out, int out_size)
{
    const float* x  = (const float*)d_in[0];
    const float* WQ = (const float*)d_in[1];
    const float* WK = (const float*)d_in[2];
    const float* WV = (const float*)d_in[3];
    const float* WO = (const float*)d_in[4];
    const float* bO = (const float*)d_in[5];
    float* out = (float*)d_out;

    __nv_bfloat16 *xhi, *xlo, *Wqhi, *Wqlo, *Wkhi, *Wklo, *Wvhi, *Wvlo, *Wohi, *Wolo;
    __nv_bfloat16 *Qhi, *Qlo, *Khi, *Klo, *Vthi, *Vtlo, *Phi, *Plo, *Ohi, *Olo;
    float* Pf;
    cudaGetSymbolAddress((void**)&xhi, g_xhi);   cudaGetSymbolAddress((void**)&xlo, g_xlo);
    cudaGetSymbolAddress((void**)&Wqhi, g_Wqhi); cudaGetSymbolAddress((void**)&Wqlo, g_Wqlo);
    cudaGetSymbolAddress((void**)&Wkhi, g_Wkhi); cudaGetSymbolAddress((void**)&Wklo, g_Wklo);
    cudaGetSymbolAddress((void**)&Wvhi, g_Wvhi); cudaGetSymbolAddress((void**)&Wvlo, g_Wvlo);
    cudaGetSymbolAddress((void**)&Wohi, g_Wohi); cudaGetSymbolAddress((void**)&Wolo, g_Wolo);
    cudaGetSymbolAddress((void**)&Qhi, g_Qhi);   cudaGetSymbolAddress((void**)&Qlo, g_Qlo);
    cudaGetSymbolAddress((void**)&Khi, g_Khi);   cudaGetSymbolAddress((void**)&Klo, g_Klo);
    cudaGetSymbolAddress((void**)&Vthi, g_Vthi); cudaGetSymbolAddress((void**)&Vtlo, g_Vtlo);
    cudaGetSymbolAddress((void**)&Phi, g_Phi);   cudaGetSymbolAddress((void**)&Plo, g_Plo);
    cudaGetSymbolAddress((void**)&Ohi, g_Ohi);   cudaGetSymbolAddress((void**)&Olo, g_Olo);
    cudaGetSymbolAddress((void**)&Pf, g_Pf);

    cudaFuncSetAttribute(k_tc<1,false,false,false>, cudaFuncAttributeMaxDynamicSharedMemorySize, SMEM_BYTES);
    cudaFuncSetAttribute(k_tc<2,false,false,false>, cudaFuncAttributeMaxDynamicSharedMemorySize, SMEM_BYTES);
    cudaFuncSetAttribute(k_tc<0,true ,false,false>, cudaFuncAttributeMaxDynamicSharedMemorySize, SMEM_BYTES);
    cudaFuncSetAttribute(k_tc<1,false,true ,false>, cudaFuncAttributeMaxDynamicSharedMemorySize, SMEM_BYTES);
    cudaFuncSetAttribute(k_tc<0,false,false,true >, cudaFuncAttributeMaxDynamicSharedMemorySize, SMEM_BYTES);

    // 1. Split inputs to bf16 hi/lo
    k_split<<<(MROWS*DIM + 255)/256, 256>>>(x,  xhi,  xlo,  MROWS*DIM);
    k_split<<<(DIM*DIM + 255)/256, 256>>>(WQ, Wqhi, Wqlo, DIM*DIM);
    k_split<<<(DIM*DIM + 255)/256, 256>>>(WK, Wkhi, Wklo, DIM*DIM);
    k_split<<<(DIM*DIM + 255)/256, 256>>>(WV, Wvhi, Wvlo, DIM*DIM);
    k_split<<<(DIM*DIM + 255)/256, 256>>>(WO, Wohi, Wolo, DIM*DIM);

    // 2. Projections: [8192,1024] x [1024,1024]^T
    dim3 gproj(DIM/128, MROWS/128, 1);
    k_tc<1,false,false,false><<<gproj, 256, SMEM_BYTES>>>(
        xhi, xlo, Wqhi, Wqlo, nullptr, Qhi, Qlo, nullptr, DIM, DIM, 0, 0, 0);
    k_tc<1,false,false,false><<<gproj, 256, SMEM_BYTES>>>(
        xhi, xlo, Wkhi, Wklo, nullptr, Khi, Klo, nullptr, DIM, DIM, 0, 0, 0);
    k_tc<2,false,false,false><<<gproj, 256, SMEM_BYTES>>>(
        xhi, xlo, Wvhi, Wvlo, nullptr, Vthi, Vtlo, nullptr, DIM, DIM, 0, 0, 0);

    // 3. Causal scores: per batch, skip tiles above diagonal
    k_tc<0,true,false,false><<<dim3(SEQ/128, SEQ/128, BATCH), 256, SMEM_BYTES>>>(
        Qhi, Qlo, Khi, Klo, Pf, nullptr, nullptr, nullptr,
        SEQ, DIM, (long long)SEQ*DIM, (long long)SEQ*DIM, (long long)SEQ*SEQ);

    // 4. Softmax (bf16 hi/lo weights, zero-padded to tile boundary)
    k_softmax<<<dim3(SEQ, 1, BATCH), 256>>>(Pf, Phi, Plo, SEQ);

    // 5. PV: O = P @ Vt^T, K bounded at causal tile edge
    k_tc<1,false,true,false><<<dim3(DIM/128, SEQ/128, BATCH), 256, SMEM_BYTES>>>(
        Phi, Plo, Vthi, Vtlo, nullptr, Ohi, Olo, nullptr,
        DIM, SEQ, (long long)SEQ*SEQ, (long long)DIM*SEQ, (long long)SEQ*DIM);

    // 6. Output projection + bias (fp32 out)
    k_tc<0,false,false,true><<<gproj, 256, SMEM_BYTES>>>(
        Ohi, Olo, Wohi, Wolo, out, nullptr, nullptr, bO, DIM, DIM, 0, 0, 0);
}

// round 4
// speedup vs baseline: 3.1518x; 1.1592x over previous
#include <cuda_runtime.h>
#include <cuda_bf16.h>
#include <math.h>
#include <stdint.h>

#define BATCH 4
#define SEQ   2048
#define DIM   1024
#define MROWS (BATCH*SEQ)   // 8192

// ---------------------------------------------------------------------------
// Scratch (__device__ globals; runtime allocation is forbidden)
// ---------------------------------------------------------------------------
__device__ __nv_bfloat16 g_xhi[MROWS*DIM],  g_xlo[MROWS*DIM];
__device__ __nv_bfloat16 g_Wqhi[DIM*DIM],   g_Wqlo[DIM*DIM];
__device__ __nv_bfloat16 g_Wkhi[DIM*DIM],   g_Wklo[DIM*DIM];
__device__ __nv_bfloat16 g_Wvhi[DIM*DIM],   g_Wvlo[DIM*DIM];
__device__ __nv_bfloat16 g_Wohi[DIM*DIM],   g_Wolo[DIM*DIM];
__device__ __nv_bfloat16 g_Qhi[MROWS*DIM],  g_Qlo[MROWS*DIM];
__device__ __nv_bfloat16 g_Khi[MROWS*DIM],  g_Klo[MROWS*DIM];
__device__ __nv_bfloat16 g_Vthi[MROWS*DIM], g_Vtlo[MROWS*DIM];   // [B, D, S]
__device__ float         g_Pf[(size_t)BATCH*SEQ*SEQ];
__device__ __nv_bfloat16 g_Phi[(size_t)BATCH*SEQ*SEQ], g_Plo[(size_t)BATCH*SEQ*SEQ];
__device__ __nv_bfloat16 g_Ohi[MROWS*DIM],  g_Olo[MROWS*DIM];

// ---------------------------------------------------------------------------
// Helpers
// ---------------------------------------------------------------------------
__device__ __forceinline__ uint32_t smem_u32(const void* p) {
    uint32_t a;
    asm("{ .reg .u64 t; cvta.to.shared.u64 t, %1; cvt.u32.u64 %0, t; }" : "=r"(a) : "l"(p));
    return a;
}

// XOR swizzle for 64B-row tiles (8 rows x 64B atom): conflict-free ldmatrix
#define SWZ64(off) ((uint32_t)(off) ^ (((uint32_t)(off) >> 3) & 0x30))

#define CP16(dst, src) \
    asm volatile("cp.async.cg.shared.global [%0], [%1], 16;" :: "r"(dst), "l"(src))
#define CPCOMMIT() asm volatile("cp.async.commit_group;" ::: "memory")
#define CPWAIT(n)  asm volatile("cp.async.wait_group %0;" :: "n"(n) : "memory")

__device__ __forceinline__ void ldm4(uint32_t* r, uint32_t addr) {
    asm volatile("ldmatrix.sync.aligned.m8n8.x4.shared.b16 {%0,%1,%2,%3}, [%4];"
        : "=r"(r[0]), "=r"(r[1]), "=r"(r[2]), "=r"(r[3]) : "r"(addr));
}

__device__ __forceinline__ void mma16816(float* c, const uint32_t* a, const uint32_t* b) {
    asm volatile("mma.sync.aligned.m16n8k16.row.col.f32.bf16.bf16.f32 "
        "{%0,%1,%2,%3}, {%4,%5,%6,%7}, {%8,%9}, {%0,%1,%2,%3};"
        : "+f"(c[0]), "+f"(c[1]), "+f"(c[2]), "+f"(c[3])
        : "r"(a[0]), "r"(a[1]), "r"(a[2]), "r"(a[3]), "r"(b[0]), "r"(b[1]));
}

// ---------------------------------------------------------------------------
// Tensor-core GEMM: C(128x128) = A * B^T, 3-MMA bf16 split precision.
// A: [rows, Kdim] hi/lo bf16 K-major; B: [rows, Kdim] hi/lo bf16 K-major.
// EPI: 0 = fp32 out (+bias), 1 = bf16 hi/lo out, 2 = bf16 hi/lo transposed (V)
// ---------------------------------------------------------------------------
#define STAGE_BYTES 32768
#define OFF_AHI 0
#define OFF_ALO 8192
#define OFF_BHI 16384
#define OFF_BLO 24576
#define SMEM_BYTES 65536
#define TPITCH 136   // transpose staging pitch (bf16 elements)

template<int EPI, bool CAUSAL, bool KBOUND, bool HASBIAS>
__global__ void __launch_bounds__(256, 2)
k_tc(const __nv_bfloat16* __restrict__ Ahi, const __nv_bfloat16* __restrict__ Alo,
     const __nv_bfloat16* __restrict__ Bhi, const __nv_bfloat16* __restrict__ Blo,
     float* __restrict__ Cf, __nv_bfloat16* __restrict__ Chi, __nv_bfloat16* __restrict__ Clo,
     const float* __restrict__ bias,
     int N, int Kdim, long long sA, long long sB, long long sC)
{
    const int m0 = blockIdx.y * 128;
    const int n0 = blockIdx.x * 128;
    if (CAUSAL && n0 > m0) return;
    const long long b = blockIdx.z;
    Ahi += b * sA; Alo += b * sA;
    Bhi += b * sB; Blo += b * sB;

    extern __shared__ char smem[];
    const uint32_t sb = smem_u32(smem);
    const int tid = threadIdx.x, lane = tid & 31, wid = tid >> 5;
    const int wm = wid & 1, wn = wid >> 1;     // warp tile 64(m) x 32(n)

    const int kend = KBOUND ? (m0 + 128) : Kdim;
    const int nchunk = kend >> 5;              // BK = 32

    float acc[4][4][4];
    #pragma unroll
    for (int i = 0; i < 4; ++i)
        #pragma unroll
        for (int j = 0; j < 4; ++j)
            #pragma unroll
            for (int r = 0; r < 4; ++r) acc[i][j][r] = 0.f;

    // stage loader: 4 tiles of 128 rows x 64B, SWZ64 layout, cp.async 16B
    auto load_stage = [&](int c, int s) {
        const int k0 = c << 5;
        const uint32_t sbase = sb + s * STAGE_BYTES;
        #pragma unroll
        for (int h = 0; h < 2; ++h) {
            const int idx = tid + h * 256;     // 0..511
            const int row = idx >> 2, ch = idx & 3;
            const uint32_t so = SWZ64(row * 64 + ch * 16);
            const size_t gA = (size_t)(m0 + row) * Kdim + k0 + ch * 8;
            const size_t gB = (size_t)(n0 + row) * Kdim + k0 + ch * 8;
            CP16(sbase + OFF_AHI + so, Ahi + gA);
            CP16(sbase + OFF_ALO + so, Alo + gA);
            CP16(sbase + OFF_BHI + so, Bhi + gB);
            CP16(sbase + OFF_BLO + so, Blo + gB);
        }
    };

    load_stage(0, 0); CPCOMMIT();

    for (int c = 0; c < nchunk; ++c) {
        const int s = c & 1;
        if (c + 1 < nchunk) { load_stage(c + 1, s ^ 1); CPCOMMIT(); CPWAIT(1); }
        else CPWAIT(0);
        __syncthreads();

        const uint32_t sA = sb + s * STAGE_BYTES;
        #pragma unroll
        for (int kk = 0; kk < 32; kk += 16) {
            // B fragments: all 4 nt tiles (hi+lo), 16 regs
            uint32_t bhi[4][2], blo[4][2];
            const int brow  = (lane & 7) + ((lane & 16) ? 8 : 0);
            const int bkoff = (lane & 8) ? 8 : 0;
            #pragma unroll
            for (int np = 0; np < 2; ++np) {
                const uint32_t off = SWZ64((wn*32 + np*16 + brow) * 64 + (kk + bkoff) * 2);
                uint32_t t4[4];
                ldm4(t4, sA + OFF_BHI + off);
                bhi[np*2][0] = t4[0]; bhi[np*2][1] = t4[1];
                bhi[np*2+1][0] = t4[2]; bhi[np*2+1][1] = t4[3];
                ldm4(t4, sA + OFF_BLO + off);
                blo[np*2][0] = t4[0]; blo[np*2][1] = t4[1];
                blo[np*2+1][0] = t4[2]; blo[np*2+1][1] = t4[3];
            }
            // Stream A fragments one mt at a time (register pressure)
            const int arow  = lane & 15;
            const int akoff = (lane >> 4) << 3;
            #pragma unroll
            for (int mt = 0; mt < 4; ++mt) {
                uint32_t ahi[4], alo[4];
                const uint32_t off = SWZ64((wm*64 + mt*16 + arow) * 64 + (kk + akoff) * 2);
                ldm4(ahi, sA + OFF_AHI + off);
                ldm4(alo, sA + OFF_ALO + off);
                #pragma unroll
                for (int nt = 0; nt < 4; ++nt) {
                    mma16816(acc[mt][nt], ahi, bhi[nt]);
                    mma16816(acc[mt][nt], ahi, blo[nt]);
                    mma16816(acc[mt][nt], alo, bhi[nt]);
                }
            }
        }
        __syncthreads();
    }

    // Epilogue. C frag: (c0,c1) row g cols t*2,t*2+1; (c2,c3) row g+8.
    const int g = lane >> 2, t = lane & 3;
    if (EPI == 2) {
        // smem-staged transpose: tile [n][m] with pitch, coalesced stores along s.
        __nv_bfloat16* tsm = (__nv_bfloat16*)smem;
        const int bb = m0 >> 11, sbase_s = m0 & 2047;
        #pragma unroll
        for (int comp = 0; comp < 2; ++comp) {
            #pragma unroll
            for (int mt = 0; mt < 4; ++mt)
                #pragma unroll
                for (int nt = 0; nt < 4; ++nt)
                    #pragma unroll
                    for (int h = 0; h < 2; ++h) {
                        const int ml = wm*64 + mt*16 + g + h*8;
                        const int nl = wn*32 + nt*8 + t*2;
                        float v0 = acc[mt][nt][h*2], v1 = acc[mt][nt][h*2+1];
                        __nv_bfloat16 o0, o1;
                        if (comp == 0) { o0 = __float2bfloat16(v0); o1 = __float2bfloat16(v1); }
                        else {
                            __nv_bfloat16 h0 = __float2bfloat16(v0), h1 = __float2bfloat16(v1);
                            o0 = __float2bfloat16(v0 - __bfloat162float(h0));
                            o1 = __float2bfloat16(v1 - __bfloat162float(h1));
                        }
                        tsm[(size_t)nl * TPITCH + ml]     = o0;
                        tsm[(size_t)(nl+1) * TPITCH + ml] = o1;
                    }
            __syncthreads();
            __nv_bfloat16* dst = (comp == 0) ? Chi : Clo;
            // 256 threads: each writes 64 contiguous bf16 (4x uint4)
            const int nl = tid >> 1, mh = (tid & 1) * 64;
            const __nv_bfloat16* srow = tsm + (size_t)nl * TPITCH + mh;
            __nv_bfloat16* drow = dst + ((size_t)bb * DIM + (n0 + nl)) * SEQ + sbase_s + mh;
            #pragma unroll
            for (int q = 0; q < 8; ++q)
                *(uint4*)(drow + q*8) = *(const uint4*)(srow + q*8);
            __syncthreads();
        }
        return;
    }
    #pragma unroll
    for (int mt = 0; mt < 4; ++mt)
        #pragma unroll
        for (int nt = 0; nt < 4; ++nt)
            #pragma unroll
            for (int h = 0; h < 2; ++h) {
                const int m  = m0 + wm*64 + mt*16 + g + h*8;
                const int nb = n0 + wn*32 + nt*8 + t*2;
                float v0 = acc[mt][nt][h*2], v1 = acc[mt][nt][h*2+1];
                if (EPI == 0) {
                    if (HASBIAS) { v0 += bias[nb]; v1 += bias[nb+1]; }
                    float* o = Cf + b*sC + (size_t)m*N + nb;
                    o[0] = v0; o[1] = v1;
                } else {
                    const size_t base = (size_t)(b*sC) + (size_t)m*N + nb;
                    __nv_bfloat16 h0 = __float2bfloat16(v0), h1 = __float2bfloat16(v1);
                    Chi[base]   = h0; Chi[base+1] = h1;
                    Clo[base]   = __float2bfloat16(v0 - __bfloat162float(h0));
                    Clo[base+1] = __float2bfloat16(v1 - __bfloat162float(h1));
                }
            }
}

// ---------------------------------------------------------------------------
// fp32 -> (bf16 hi, bf16 lo) split, 4 elements per thread
// ---------------------------------------------------------------------------
__global__ void __launch_bounds__(256)
k_split(const float* __restrict__ src, __nv_bfloat16* __restrict__ hi,
        __nv_bfloat16* __restrict__ lo, int n)
{
    int i = (blockIdx.x * 256 + threadIdx.x) * 4;
    if (i < n) {
        float4 v = *(const float4*)(src + i);
        __nv_bfloat16 h0 = __float2bfloat16(v.x), h1 = __float2bfloat16(v.y);
        __nv_bfloat16 h2 = __float2bfloat16(v.z), h3 = __float2bfloat16(v.w);
        __nv_bfloat162* ph = (__nv_bfloat162*)(hi + i);
        ph[0] = __nv_bfloat162(h0, h1); ph[1] = __nv_bfloat162(h2, h3);
        __nv_bfloat162* pl = (__nv_bfloat162*)(lo + i);
        pl[0] = __nv_bfloat162(__float2bfloat16(v.x - __bfloat162float(h0)),
                               __float2bfloat16(v.y - __bfloat162float(h1)));
        pl[1] = __nv_bfloat162(__float2bfloat16(v.z - __bfloat162float(h2)),
                               __float2bfloat16(v.w - __bfloat162float(h3)));
    }
}

// ---------------------------------------------------------------------------
// Causal row softmax: fp32 scores -> bf16 hi/lo weights, zero-padded to the
// next 128 boundary (so PV can bound its K loop at the tile edge).
// ---------------------------------------------------------------------------
__global__ void __launch_bounds__(256)
k_softmax(const float* __restrict__ Pf, __nv_bfloat16* __restrict__ Phi,
          __nv_bfloat16* __restrict__ Plo, int S)
{
    const int b = blockIdx.z;
    const int row = blockIdx.x;
    const float* r = Pf + ((size_t)b * S + row) * S;
    __nv_bfloat16* oh = Phi + ((size_t)b * S + row) * S;
    __nv_bfloat16* ol = Plo + ((size_t)b * S + row) * S;
    const int len = row + 1;
    const int tid = threadIdx.x;

    __shared__ float red[8];

    float m = -INFINITY;
    for (int i = tid; i < len; i += 256) m = fmaxf(m, r[i]);
    #pragma unroll
    for (int o = 16; o; o >>= 1) m = fmaxf(m, __shfl_xor_sync(0xffffffffu, m, o));
    if ((tid & 31) == 0) red[tid >> 5] = m;
    __syncthreads();
    float mm = -INFINITY;
    #pragma unroll
    for (int i = 0; i < 8; ++i) mm = fmaxf(mm, red[i]);
    __syncthreads();

    float s = 0.f;
    for (int i = tid; i < len; i += 256) s += __expf(r[i] - mm);
    #pragma unroll
    for (int o = 16; o; o >>= 1) s += __shfl_xor_sync(0xffffffffu, s, o);
    if ((tid & 31) == 0) red[tid >> 5] = s;
    __syncthreads();
    float ss = 0.f;
    #pragma unroll
    for (int i = 0; i < 8; ++i) ss += red[i];
    const float inv = 1.f / ss;

    for (int i = tid; i < len; i += 256) {
        float p = __expf(r[i] - mm) * inv;
        __nv_bfloat16 h = __float2bfloat16(p);
        oh[i] = h;
        ol[i] = __float2bfloat16(p - __bfloat162float(h));
    }
    const int zend = ((row >> 7) + 1) << 7;
    for (int i = len + tid; i < zend; i += 256) {
        oh[i] = __float2bfloat16(0.f);
        ol[i] = __float2bfloat16(0.f);
    }
}

// ---------------------------------------------------------------------------
extern "C" void kernel_launch(void* const* d_in, const int* in_sizes, int n_in,
                              void* d_out, int out_size)
{
    const float* x  = (const float*)d_in[0];
    const float* WQ = (const float*)d_in[1];
    const float* WK = (const float*)d_in[2];
    const float* WV = (const float*)d_in[3];
    const float* WO = (const float*)d_in[4];
    const float* bO = (const float*)d_in[5];
    float* out = (float*)d_out;

    __nv_bfloat16 *xhi, *xlo, *Wqhi, *Wqlo, *Wkhi, *Wklo, *Wvhi, *Wvlo, *Wohi, *Wolo;
    __nv_bfloat16 *Qhi, *Qlo, *Khi, *Klo, *Vthi, *Vtlo, *Phi, *Plo, *Ohi, *Olo;
    float* Pf;
    cudaGetSymbolAddress((void**)&xhi, g_xhi);   cudaGetSymbolAddress((void**)&xlo, g_xlo);
    cudaGetSymbolAddress((void**)&Wqhi, g_Wqhi); cudaGetSymbolAddress((void**)&Wqlo, g_Wqlo);
    cudaGetSymbolAddress((void**)&Wkhi, g_Wkhi); cudaGetSymbolAddress((void**)&Wklo, g_Wklo);
    cudaGetSymbolAddress((void**)&Wvhi, g_Wvhi); cudaGetSymbolAddress((void**)&Wvlo, g_Wvlo);
    cudaGetSymbolAddress((void**)&Wohi, g_Wohi); cudaGetSymbolAddress((void**)&Wolo, g_Wolo);
    cudaGetSymbolAddress((void**)&Qhi, g_Qhi);   cudaGetSymbolAddress((void**)&Qlo, g_Qlo);
    cudaGetSymbolAddress((void**)&Khi, g_Khi);   cudaGetSymbolAddress((void**)&Klo, g_Klo);
    cudaGetSymbolAddress((void**)&Vthi, g_Vthi); cudaGetSymbolAddress((void**)&Vtlo, g_Vtlo);
    cudaGetSymbolAddress((void**)&Phi, g_Phi);   cudaGetSymbolAddress((void**)&Plo, g_Plo);
    cudaGetSymbolAddress((void**)&Ohi, g_Ohi);   cudaGetSymbolAddress((void**)&Olo, g_Olo);
    cudaGetSymbolAddress((void**)&Pf, g_Pf);

    cudaFuncSetAttribute(k_tc<1,false,false,false>, cudaFuncAttributeMaxDynamicSharedMemorySize, SMEM_BYTES);
    cudaFuncSetAttribute(k_tc<2,false,false,false>, cudaFuncAttributeMaxDynamicSharedMemorySize, SMEM_BYTES);
    cudaFuncSetAttribute(k_tc<0,true ,false,false>, cudaFuncAttributeMaxDynamicSharedMemorySize, SMEM_BYTES);
    cudaFuncSetAttribute(k_tc<1,false,true ,false>, cudaFuncAttributeMaxDynamicSharedMemorySize, SMEM_BYTES);
    cudaFuncSetAttribute(k_tc<0,false,false,true >, cudaFuncAttributeMaxDynamicSharedMemorySize, SMEM_BYTES);

    // 1. Split inputs to bf16 hi/lo
    k_split<<<(MROWS*DIM/4 + 255)/256, 256>>>(x,  xhi,  xlo,  MROWS*DIM);
    k_split<<<(DIM*DIM/4 + 255)/256, 256>>>(WQ, Wqhi, Wqlo, DIM*DIM);
    k_split<<<(DIM*DIM/4 + 255)/256, 256>>>(WK, Wkhi, Wklo, DIM*DIM);
    k_split<<<(DIM*DIM/4 + 255)/256, 256>>>(WV, Wvhi, Wvlo, DIM*DIM);
    k_split<<<(DIM*DIM/4 + 255)/256, 256>>>(WO, Wohi, Wolo, DIM*DIM);

    // 2. Projections: [8192,1024] x [1024,1024]^T
    dim3 gproj(DIM/128, MROWS/128, 1);
    k_tc<1,false,false,false><<<gproj, 256, SMEM_BYTES>>>(
        xhi, xlo, Wqhi, Wqlo, nullptr, Qhi, Qlo, nullptr, DIM, DIM, 0, 0, 0);
    k_tc<1,false,false,false><<<gproj, 256, SMEM_BYTES>>>(
        xhi, xlo, Wkhi, Wklo, nullptr, Khi, Klo, nullptr, DIM, DIM, 0, 0, 0);
    k_tc<2,false,false,false><<<gproj, 256, SMEM_BYTES>>>(
        xhi, xlo, Wvhi, Wvlo, nullptr, Vthi, Vtlo, nullptr, DIM, DIM, 0, 0, 0);

    // 3. Causal scores: per batch, skip tiles above diagonal
    k_tc<0,true,false,false><<<dim3(SEQ/128, SEQ/128, BATCH), 256, SMEM_BYTES>>>(
        Qhi, Qlo, Khi, Klo, Pf, nullptr, nullptr, nullptr,
        SEQ, DIM, (long long)SEQ*DIM, (long long)SEQ*DIM, (long long)SEQ*SEQ);

    // 4. Softmax (bf16 hi/lo weights, zero-padded to tile boundary)
    k_softmax<<<dim3(SEQ, 1, BATCH), 256>>>(Pf, Phi, Plo, SEQ);

    // 5. PV: O = P @ Vt^T, K bounded at causal tile edge
    k_tc<1,false,true,false><<<dim3(DIM/128, SEQ/128, BATCH), 256, SMEM_BYTES>>>(
        Phi, Plo, Vthi, Vtlo, nullptr, Ohi, Olo, nullptr,
        DIM, SEQ, (long long)SEQ*SEQ, (long long)DIM*SEQ, (long long)SEQ*DIM);

    // 6. Output projection + bias (fp32 out)
    k_tc<0,false,false,true><<<gproj, 256, SMEM_BYTES>>>(
        Ohi, Olo, Wohi, Wolo, out, nullptr, nullptr, bO, DIM, DIM, 0, 0, 0);
}

// round 5
// speedup vs baseline: 3.4484x; 1.0941x over previous
#include <cuda_runtime.h>
#include <cuda_bf16.h>
#include <math.h>
#include <stdint.h>

#define BATCH 4
#define SEQ   2048
#define DIM   1024
#define MROWS (BATCH*SEQ)   // 8192

// ---------------------------------------------------------------------------
// Scratch (__device__ globals; runtime allocation is forbidden)
// ---------------------------------------------------------------------------
__device__ __nv_bfloat16 g_xhi[MROWS*DIM],  g_xlo[MROWS*DIM];
__device__ __nv_bfloat16 g_Wqkvhi[3*DIM*DIM], g_Wqkvlo[3*DIM*DIM];  // stacked Q,K,V
__device__ __nv_bfloat16 g_Wohi[DIM*DIM],   g_Wolo[DIM*DIM];
__device__ __nv_bfloat16 g_Qhi[MROWS*DIM],  g_Qlo[MROWS*DIM];
__device__ __nv_bfloat16 g_Khi[MROWS*DIM],  g_Klo[MROWS*DIM];
__device__ __nv_bfloat16 g_Vthi[MROWS*DIM], g_Vtlo[MROWS*DIM];   // [B, D, S]
__device__ float         g_Pf[(size_t)BATCH*SEQ*SEQ];
__device__ __nv_bfloat16 g_Phi[(size_t)BATCH*SEQ*SEQ], g_Plo[(size_t)BATCH*SEQ*SEQ];
__device__ __nv_bfloat16 g_Ohi[MROWS*DIM],  g_Olo[MROWS*DIM];

// ---------------------------------------------------------------------------
// Helpers
// ---------------------------------------------------------------------------
__device__ __forceinline__ uint32_t smem_u32(const void* p) {
    uint32_t a;
    asm("{ .reg .u64 t; cvta.to.shared.u64 t, %1; cvt.u32.u64 %0, t; }" : "=r"(a) : "l"(p));
    return a;
}

// XOR swizzle for 64B-row tiles (8 rows x 64B atom): conflict-free ldmatrix
#define SWZ64(off) ((uint32_t)(off) ^ (((uint32_t)(off) >> 3) & 0x30))

#define CP16(dst, src) \
    asm volatile("cp.async.cg.shared.global [%0], [%1], 16;" :: "r"(dst), "l"(src))
#define CPCOMMIT() asm volatile("cp.async.commit_group;" ::: "memory")
#define CPWAIT(n)  asm volatile("cp.async.wait_group %0;" :: "n"(n) : "memory")

__device__ __forceinline__ void ldm4(uint32_t* r, uint32_t addr) {
    asm volatile("ldmatrix.sync.aligned.m8n8.x4.shared.b16 {%0,%1,%2,%3}, [%4];"
        : "=r"(r[0]), "=r"(r[1]), "=r"(r[2]), "=r"(r[3]) : "r"(addr));
}

__device__ __forceinline__ void mma16816(float* c, const uint32_t* a, const uint32_t* b) {
    asm volatile("mma.sync.aligned.m16n8k16.row.col.f32.bf16.bf16.f32 "
        "{%0,%1,%2,%3}, {%4,%5,%6,%7}, {%8,%9}, {%0,%1,%2,%3};"
        : "+f"(c[0]), "+f"(c[1]), "+f"(c[2]), "+f"(c[3])
        : "r"(a[0]), "r"(a[1]), "r"(a[2]), "r"(a[3]), "r"(b[0]), "r"(b[1]));
}

// ---------------------------------------------------------------------------
// Tensor-core GEMM: C(128x128) = A * B^T, 3-MMA bf16 split precision.
// EPI: 0 = fp32 out (+bias), 1 = bf16 hi/lo out, 3 = QKV-routed (Q/K direct,
//      V transposed via smem staging)
// ---------------------------------------------------------------------------
#define STAGE_BYTES 32768
#define OFF_AHI 0
#define OFF_ALO 8192
#define OFF_BHI 16384
#define OFF_BLO 24576
#define NSTAGE 3
#define SMEM_BYTES (NSTAGE*STAGE_BYTES)   // 98304
#define TPITCH 136   // transpose staging pitch (bf16 elements)

template<int EPI, bool CAUSAL, bool KBOUND, bool HASBIAS, bool REV>
__global__ void __launch_bounds__(256, 2)
k_tc(const __nv_bfloat16* __restrict__ Ahi, const __nv_bfloat16* __restrict__ Alo,
     const __nv_bfloat16* __restrict__ Bhi, const __nv_bfloat16* __restrict__ Blo,
     float* __restrict__ Cf, __nv_bfloat16* __restrict__ Chi, __nv_bfloat16* __restrict__ Clo,
     const float* __restrict__ bias,
     int N, int Kdim, long long sA, long long sB, long long sC)
{
    const int by = REV ? (gridDim.y - 1 - blockIdx.y) : blockIdx.y;
    const int m0 = by * 128;
    const int n0 = blockIdx.x * 128;
    if (CAUSAL && n0 > m0) return;
    const long long b = blockIdx.z;
    Ahi += b * sA; Alo += b * sA;
    Bhi += b * sB; Blo += b * sB;

    extern __shared__ char smem[];
    const uint32_t sb = smem_u32(smem);
    const int tid = threadIdx.x, lane = tid & 31, wid = tid >> 5;
    const int wm = wid & 1, wn = wid >> 1;     // warp tile 64(m) x 32(n)

    const int kend = KBOUND ? (m0 + 128) : Kdim;
    const int nchunk = kend >> 5;              // BK = 32

    float acc[4][4][4];
    #pragma unroll
    for (int i = 0; i < 4; ++i)
        #pragma unroll
        for (int j = 0; j < 4; ++j)
            #pragma unroll
            for (int r = 0; r < 4; ++r) acc[i][j][r] = 0.f;

    // stage loader: 4 tiles of 128 rows x 64B, SWZ64 layout, cp.async 16B
    auto load_stage = [&](int c, int s) {
        const int k0 = c << 5;
        const uint32_t sbase = sb + s * STAGE_BYTES;
        #pragma unroll
        for (int h = 0; h < 2; ++h) {
            const int idx = tid + h * 256;     // 0..511
            const int row = idx >> 2, ch = idx & 3;
            const uint32_t so = SWZ64(row * 64 + ch * 16);
            const size_t gA = (size_t)(m0 + row) * Kdim + k0 + ch * 8;
            const size_t gB = (size_t)(n0 + row) * Kdim + k0 + ch * 8;
            CP16(sbase + OFF_AHI + so, Ahi + gA);
            CP16(sbase + OFF_ALO + so, Alo + gA);
            CP16(sbase + OFF_BHI + so, Bhi + gB);
            CP16(sbase + OFF_BLO + so, Blo + gB);
        }
    };

    load_stage(0, 0); CPCOMMIT();
    if (nchunk > 1) { load_stage(1, 1); CPCOMMIT(); }

    for (int c = 0; c < nchunk; ++c) {
        if (c + 2 < nchunk) { load_stage(c + 2, (c + 2) % NSTAGE); CPCOMMIT(); }
        if (c + 2 < nchunk) CPWAIT(2);
        else if (c + 1 < nchunk) CPWAIT(1);
        else CPWAIT(0);
        __syncthreads();

        const uint32_t sA = sb + (c % NSTAGE) * STAGE_BYTES;
        #pragma unroll
        for (int kk = 0; kk < 32; kk += 16) {
            // B fragments: all 4 nt tiles (hi+lo), 16 regs
            uint32_t bhi[4][2], blo[4][2];
            const int brow  = (lane & 7) + ((lane & 16) ? 8 : 0);
            const int bkoff = (lane & 8) ? 8 : 0;
            #pragma unroll
            for (int np = 0; np < 2; ++np) {
                const uint32_t off = SWZ64((wn*32 + np*16 + brow) * 64 + (kk + bkoff) * 2);
                uint32_t t4[4];
                ldm4(t4, sA + OFF_BHI + off);
                bhi[np*2][0] = t4[0]; bhi[np*2][1] = t4[1];
                bhi[np*2+1][0] = t4[2]; bhi[np*2+1][1] = t4[3];
                ldm4(t4, sA + OFF_BLO + off);
                blo[np*2][0] = t4[0]; blo[np*2][1] = t4[1];
                blo[np*2+1][0] = t4[2]; blo[np*2+1][1] = t4[3];
            }
            // Stream A fragments one mt at a time (register pressure)
            const int arow  = lane & 15;
            const int akoff = (lane >> 4) << 3;
            #pragma unroll
            for (int mt = 0; mt < 4; ++mt) {
                uint32_t ahi[4], alo[4];
                const uint32_t off = SWZ64((wm*64 + mt*16 + arow) * 64 + (kk + akoff) * 2);
                ldm4(ahi, sA + OFF_AHI + off);
                ldm4(alo, sA + OFF_ALO + off);
                #pragma unroll
                for (int nt = 0; nt < 4; ++nt) {
                    mma16816(acc[mt][nt], ahi, bhi[nt]);
                    mma16816(acc[mt][nt], ahi, blo[nt]);
                    mma16816(acc[mt][nt], alo, bhi[nt]);
                }
            }
        }
        __syncthreads();
    }

    // Epilogue. C frag: (c0,c1) row g cols t*2,t*2+1; (c2,c3) row g+8.
    const int g = lane >> 2, t = lane & 3;
    const bool vpath = (EPI == 3) && (n0 >= 2*DIM);
    if (vpath) {
        // V projection: smem-staged transpose, coalesced stores along s.
        __nv_bfloat16* tsm = (__nv_bfloat16*)smem;
        const int bb = m0 >> 11, sbase_s = m0 & 2047;
        const int nvl0 = n0 - 2*DIM;
        #pragma unroll
        for (int comp = 0; comp < 2; ++comp) {
            #pragma unroll
            for (int mt = 0; mt < 4; ++mt)
                #pragma unroll
                for (int nt = 0; nt < 4; ++nt)
                    #pragma unroll
                    for (int h = 0; h < 2; ++h) {
                        const int ml = wm*64 + mt*16 + g + h*8;
                        const int nl = wn*32 + nt*8 + t*2;
                        float v0 = acc[mt][nt][h*2], v1 = acc[mt][nt][h*2+1];
                        __nv_bfloat16 o0, o1;
                        if (comp == 0) { o0 = __float2bfloat16(v0); o1 = __float2bfloat16(v1); }
                        else {
                            __nv_bfloat16 h0 = __float2bfloat16(v0), h1 = __float2bfloat16(v1);
                            o0 = __float2bfloat16(v0 - __bfloat162float(h0));
                            o1 = __float2bfloat16(v1 - __bfloat162float(h1));
                        }
                        tsm[(size_t)nl * TPITCH + ml]     = o0;
                        tsm[(size_t)(nl+1) * TPITCH + ml] = o1;
                    }
            __syncthreads();
            __nv_bfloat16* dst = (comp == 0) ? g_Vthi : g_Vtlo;
            const int nl = tid >> 1, mh = (tid & 1) * 64;
            const __nv_bfloat16* srow = tsm + (size_t)nl * TPITCH + mh;
            __nv_bfloat16* drow = dst + ((size_t)bb * DIM + (nvl0 + nl)) * SEQ + sbase_s + mh;
            #pragma unroll
            for (int q = 0; q < 8; ++q)
                *(uint4*)(drow + q*8) = *(const uint4*)(srow + q*8);
            __syncthreads();
        }
        return;
    }
    #pragma unroll
    for (int mt = 0; mt < 4; ++mt)
        #pragma unroll
        for (int nt = 0; nt < 4; ++nt)
            #pragma unroll
            for (int h = 0; h < 2; ++h) {
                const int m  = m0 + wm*64 + mt*16 + g + h*8;
                const int nb = n0 + wn*32 + nt*8 + t*2;
                float v0 = acc[mt][nt][h*2], v1 = acc[mt][nt][h*2+1];
                if (EPI == 0) {
                    if (HASBIAS) { v0 += bias[nb]; v1 += bias[nb+1]; }
                    float* o = Cf + b*sC + (size_t)m*N + nb;
                    o[0] = v0; o[1] = v1;
                } else if (EPI == 1) {
                    const size_t base = (size_t)(b*sC) + (size_t)m*N + nb;
                    __nv_bfloat16 h0 = __float2bfloat16(v0), h1 = __float2bfloat16(v1);
                    Chi[base]   = h0; Chi[base+1] = h1;
                    Clo[base]   = __float2bfloat16(v0 - __bfloat162float(h0));
                    Clo[base+1] = __float2bfloat16(v1 - __bfloat162float(h1));
                } else {  // EPI==3, Q/K route
                    const int which = nb >> 10;         // 0=Q, 1=K
                    const int nl = nb & 1023;
                    __nv_bfloat16* dh = which ? g_Khi : g_Qhi;
                    __nv_bfloat16* dl = which ? g_Klo : g_Qlo;
                    const size_t base = (size_t)m * DIM + nl;
                    __nv_bfloat16 h0 = __float2bfloat16(v0), h1 = __float2bfloat16(v1);
                    dh[base]   = h0; dh[base+1] = h1;
                    dl[base]   = __float2bfloat16(v0 - __bfloat162float(h0));
                    dl[base+1] = __float2bfloat16(v1 - __bfloat162float(h1));
                }
            }
}

// ---------------------------------------------------------------------------
// fp32 -> (bf16 hi, bf16 lo) split, 4 elements per thread
// ---------------------------------------------------------------------------
__global__ void __launch_bounds__(256)
k_split(const float* __restrict__ src, __nv_bfloat16* __restrict__ hi,
        __nv_bfloat16* __restrict__ lo, int n)
{
    int i = (blockIdx.x * 256 + threadIdx.x) * 4;
    if (i < n) {
        float4 v = *(const float4*)(src + i);
        __nv_bfloat16 h0 = __float2bfloat16(v.x), h1 = __float2bfloat16(v.y);
        __nv_bfloat16 h2 = __float2bfloat16(v.z), h3 = __float2bfloat16(v.w);
        __nv_bfloat162* ph = (__nv_bfloat162*)(hi + i);
        ph[0] = __nv_bfloat162(h0, h1); ph[1] = __nv_bfloat162(h2, h3);
        __nv_bfloat162* pl = (__nv_bfloat162*)(lo + i);
        pl[0] = __nv_bfloat162(__float2bfloat16(v.x - __bfloat162float(h0)),
                               __float2bfloat16(v.y - __bfloat162float(h1)));
        pl[1] = __nv_bfloat162(__float2bfloat16(v.z - __bfloat162float(h2)),
                               __float2bfloat16(v.w - __bfloat162float(h3)));
    }
}

// ---------------------------------------------------------------------------
// Causal row softmax, register-cached: one global read, one exp pass, one
// write. Output bf16 hi/lo, zero-padded to the next 128 boundary.
// ---------------------------------------------------------------------------
__global__ void __launch_bounds__(256)
k_softmax(const float* __restrict__ Pf, __nv_bfloat16* __restrict__ Phi,
          __nv_bfloat16* __restrict__ Plo, int S)
{
    const int b = blockIdx.z;
    const int row = blockIdx.x;
    const float* r = Pf + ((size_t)b * S + row) * S;
    __nv_bfloat16* oh = Phi + ((size_t)b * S + row) * S;
    __nv_bfloat16* ol = Plo + ((size_t)b * S + row) * S;
    const int len = row + 1;
    const int tid = threadIdx.x;

    __shared__ float red[8];

    float xv[8];
    float m = -INFINITY;
    #pragma unroll
    for (int j = 0; j < 8; ++j) {
        const int i = tid + j * 256;
        if (i < len) { xv[j] = r[i]; m = fmaxf(m, xv[j]); }
    }
    #pragma unroll
    for (int o = 16; o; o >>= 1) m = fmaxf(m, __shfl_xor_sync(0xffffffffu, m, o));
    if ((tid & 31) == 0) red[tid >> 5] = m;
    __syncthreads();
    float mm = -INFINITY;
    #pragma unroll
    for (int i = 0; i < 8; ++i) mm = fmaxf(mm, red[i]);
    __syncthreads();

    float ev[8];
    float s = 0.f;
    #pragma unroll
    for (int j = 0; j < 8; ++j) {
        const int i = tid + j * 256;
        if (i < len) { ev[j] = __expf(xv[j] - mm); s += ev[j]; }
    }
    #pragma unroll
    for (int o = 16; o; o >>= 1) s += __shfl_xor_sync(0xffffffffu, s, o);
    if ((tid & 31) == 0) red[tid >> 5] = s;
    __syncthreads();
    float ss = 0.f;
    #pragma unroll
    for (int i = 0; i < 8; ++i) ss += red[i];
    const float inv = 1.f / ss;

    #pragma unroll
    for (int j = 0; j < 8; ++j) {
        const int i = tid + j * 256;
        if (i < len) {
            float p = ev[j] * inv;
            __nv_bfloat16 h = __float2bfloat16(p);
            oh[i] = h;
            ol[i] = __float2bfloat16(p - __bfloat162float(h));
        }
    }
    const int zend = ((row >> 7) + 1) << 7;
    for (int i = len + tid; i < zend; i += 256) {
        oh[i] = __float2bfloat16(0.f);
        ol[i] = __float2bfloat16(0.f);
    }
}

// ---------------------------------------------------------------------------
extern "C" void kernel_launch(void* const* d_in, const int* in_sizes, int n_in,
                              void* d_out, int out_size)
{
    const float* x  = (const float*)d_in[0];
    const float* WQ = (const float*)d_in[1];
    const float* WK = (const float*)d_in[2];
    const float* WV = (const float*)d_in[3];
    const float* WO = (const float*)d_in[4];
    const float* bO = (const float*)d_in[5];
    float* out = (float*)d_out;

    __nv_bfloat16 *xhi, *xlo, *Wqkvhi, *Wqkvlo, *Wohi, *Wolo;
    __nv_bfloat16 *Qhi, *Qlo, *Khi, *Klo, *Vthi, *Vtlo, *Phi, *Plo, *Ohi, *Olo;
    float* Pf;
    cudaGetSymbolAddress((void**)&xhi, g_xhi);       cudaGetSymbolAddress((void**)&xlo, g_xlo);
    cudaGetSymbolAddress((void**)&Wqkvhi, g_Wqkvhi); cudaGetSymbolAddress((void**)&Wqkvlo, g_Wqkvlo);
    cudaGetSymbolAddress((void**)&Wohi, g_Wohi);     cudaGetSymbolAddress((void**)&Wolo, g_Wolo);
    cudaGetSymbolAddress((void**)&Qhi, g_Qhi);       cudaGetSymbolAddress((void**)&Qlo, g_Qlo);
    cudaGetSymbolAddress((void**)&Khi, g_Khi);       cudaGetSymbolAddress((void**)&Klo, g_Klo);
    cudaGetSymbolAddress((void**)&Vthi, g_Vthi);     cudaGetSymbolAddress((void**)&Vtlo, g_Vtlo);
    cudaGetSymbolAddress((void**)&Phi, g_Phi);       cudaGetSymbolAddress((void**)&Plo, g_Plo);
    cudaGetSymbolAddress((void**)&Ohi, g_Ohi);       cudaGetSymbolAddress((void**)&Olo, g_Olo);
    cudaGetSymbolAddress((void**)&Pf, g_Pf);

    cudaFuncSetAttribute(k_tc<3,false,false,false,false>, cudaFuncAttributeMaxDynamicSharedMemorySize, SMEM_BYTES);
    cudaFuncSetAttribute(k_tc<0,true ,false,false,false>, cudaFuncAttributeMaxDynamicSharedMemorySize, SMEM_BYTES);
    cudaFuncSetAttribute(k_tc<1,false,true ,false,true >, cudaFuncAttributeMaxDynamicSharedMemorySize, SMEM_BYTES);
    cudaFuncSetAttribute(k_tc<0,false,false,true ,false>, cudaFuncAttributeMaxDynamicSharedMemorySize, SMEM_BYTES);

    // 1. Split inputs to bf16 hi/lo (QKV weights stacked)
    k_split<<<(MROWS*DIM/4 + 255)/256, 256>>>(x,  xhi,  xlo,  MROWS*DIM);
    k_split<<<(DIM*DIM/4 + 255)/256, 256>>>(WQ, Wqkvhi,             Wqkvlo,             DIM*DIM);
    k_split<<<(DIM*DIM/4 + 255)/256, 256>>>(WK, Wqkvhi + DIM*DIM,   Wqkvlo + DIM*DIM,   DIM*DIM);
    k_split<<<(DIM*DIM/4 + 255)/256, 256>>>(WV, Wqkvhi + 2*DIM*DIM, Wqkvlo + 2*DIM*DIM, DIM*DIM);
    k_split<<<(DIM*DIM/4 + 255)/256, 256>>>(WO, Wohi, Wolo, DIM*DIM);

    // 2. Merged QKV projection: [8192,1024] x [3072,1024]^T, routed epilogue
    k_tc<3,false,false,false,false><<<dim3(3*DIM/128, MROWS/128, 1), 256, SMEM_BYTES>>>(
        xhi, xlo, Wqkvhi, Wqkvlo, nullptr, nullptr, nullptr, nullptr,
        3*DIM, DIM, 0, 0, 0);

    // 3. Causal scores: per batch, skip tiles above diagonal
    k_tc<0,true,false,false,false><<<dim3(SEQ/128, SEQ/128, BATCH), 256, SMEM_BYTES>>>(
        Qhi, Qlo, Khi, Klo, Pf, nullptr, nullptr, nullptr,
        SEQ, DIM, (long long)SEQ*DIM, (long long)SEQ*DIM, (long long)SEQ*SEQ);

    // 4. Softmax (register-cached single-exp)
    k_softmax<<<dim3(SEQ, 1, BATCH), 256>>>(Pf, Phi, Plo, SEQ);

    // 5. PV: O = P @ Vt^T, K bounded at causal tile edge; longest blocks first
    k_tc<1,false,true,false,true><<<dim3(DIM/128, SEQ/128, BATCH), 256, SMEM_BYTES>>>(
        Phi, Plo, Vthi, Vtlo, nullptr, Ohi, Olo, nullptr,
        DIM, SEQ, (long long)SEQ*SEQ, (long long)DIM*SEQ, (long long)SEQ*DIM);

    // 6. Output projection + bias (fp32 out)
    k_tc<0,false,false,true,false><<<dim3(DIM/128, MROWS/128, 1), 256, SMEM_BYTES>>>(
        Ohi, Olo, Wohi, Wolo, out, nullptr, nullptr, bO, DIM, DIM, 0, 0, 0);
}